// round 6
// baseline (speedup 1.0000x reference)
#include <cstdint>
#include <cuda_runtime.h>
#include <cuda_bf16.h>
#include <mma.h>

using namespace nvcuda;

// ---------------- problem constants ----------------
constexpr int T   = 16384;   // B*S tokens
constexpr int Dm  = 1024;    // model dim
constexpr int DFm = 4096;    // expert hidden dim
constexpr int E   = 8;       // experts

// ---------------- GEMM tile config ----------------
constexpr int BM = 128, BN = 128, BK = 32;
constexpr int LDA = BK + 8;    // 40 floats
constexpr int LDB = BN + 4;    // 132 floats
constexpr int LDC = BN + 4;    // 132 floats
constexpr int THREADS = 256;
constexpr int STAGES = 3;

constexpr int A_SZ     = BM * LDA;              // 5120 floats
constexpr int B_SZ     = BK * LDB;              // 4224 floats
constexpr int STAGE_SZ = A_SZ + B_SZ;           // 9344 floats
constexpr int MAIN_SZ  = STAGES * STAGE_SZ;     // 28032 floats = 112128 B
constexpr int C_SZ     = BM * LDC;              // 16896 floats = 67584 B
constexpr int SMEM_BYTES = (MAIN_SZ > C_SZ ? MAIN_SZ : C_SZ) * 4;  // 112128

using FragA = wmma::fragment<wmma::matrix_a, 16, 16, 8, wmma::precision::tf32, wmma::row_major>;
using FragB = wmma::fragment<wmma::matrix_b, 16, 16, 8, wmma::precision::tf32, wmma::row_major>;
using FragC = wmma::fragment<wmma::accumulator, 16, 16, 8, float>;

// ---------------- device scratch (no allocs allowed) ----------------
__device__ int   g_counts[E];
__device__ int   g_tok[E * T];
__device__ int   g_ent[E * T];
__device__ float g_w[E * T];
__device__ float g_H[(size_t)2 * T * DFm];     // 536 MB (tf32-valued)
__device__ float g_O[(size_t)2 * T * Dm];      // 134 MB
__device__ float g_Xt[(size_t)T * Dm];         // 67 MB  (tf32-valued x)
__device__ float g_W1t[(size_t)E * Dm * DFm];  // 134 MB (tf32-valued W1)
__device__ float g_W2t[(size_t)E * DFm * Dm];  // 134 MB (tf32-valued W2)

__device__ __forceinline__ float silu_f(float v) {
    return v / (1.0f + __expf(-v));
}

#define CP_ASYNC_CG(dst_u32, src_ptr) \
    asm volatile("cp.async.cg.shared.global [%0], [%1], 16;\n" :: "r"(dst_u32), "l"(src_ptr))
#define CP_ASYNC_COMMIT()  asm volatile("cp.async.commit_group;\n" ::)
#define CP_ASYNC_WAIT_1()  asm volatile("cp.async.wait_group 1;\n" ::)
#define CP_ASYNC_WAIT_ALL() asm volatile("cp.async.wait_group 0;\n" ::)

__device__ __forceinline__ unsigned smem_u32(const void* p) {
    return static_cast<unsigned>(__cvta_generic_to_shared(p));
}

// ---------------- tf32 pre-conversion kernels ----------------
__device__ __forceinline__ float4 tf32_round4(float4 v) {
    v.x = wmma::__float_to_tf32(v.x); v.y = wmma::__float_to_tf32(v.y);
    v.z = wmma::__float_to_tf32(v.z); v.w = wmma::__float_to_tf32(v.w);
    return v;
}

__global__ __launch_bounds__(256) void cvt_x_kernel(const float* __restrict__ src) {
    int i = blockIdx.x * 256 + threadIdx.x;                 // over T*Dm/4
    if (i < T * Dm / 4)
        reinterpret_cast<float4*>(g_Xt)[i] =
            tf32_round4(reinterpret_cast<const float4*>(src)[i]);
}
__global__ __launch_bounds__(256) void cvt_w1_kernel(const float* __restrict__ src) {
    size_t i = (size_t)blockIdx.x * 256 + threadIdx.x;      // over E*Dm*DFm/4
    if (i < (size_t)E * Dm * DFm / 4)
        reinterpret_cast<float4*>(g_W1t)[i] =
            tf32_round4(reinterpret_cast<const float4*>(src)[i]);
}
__global__ __launch_bounds__(256) void cvt_w2_kernel(const float* __restrict__ src) {
    size_t i = (size_t)blockIdx.x * 256 + threadIdx.x;      // over E*DFm*Dm/4
    if (i < (size_t)E * DFm * Dm / 4)
        reinterpret_cast<float4*>(g_W2t)[i] =
            tf32_round4(reinterpret_cast<const float4*>(src)[i]);
}

// ---------------- routing ----------------
__global__ void zero_counts_kernel() {
    if (threadIdx.x < E) g_counts[threadIdx.x] = 0;
}

__global__ __launch_bounds__(256) void route_kernel(const float* __restrict__ x,
                                                    const float* __restrict__ gw) {
    int t    = (blockIdx.x * blockDim.x + threadIdx.x) >> 5;
    int lane = threadIdx.x & 31;
    if (t >= T) return;
    const float* xr = x + (size_t)t * Dm;

    float acc[E];
#pragma unroll
    for (int e = 0; e < E; e++) acc[e] = 0.0f;
    for (int c = lane; c < Dm; c += 32) {
        float xv = __ldg(xr + c);
#pragma unroll
        for (int e = 0; e < E; e++) acc[e] = fmaf(xv, __ldg(gw + e * Dm + c), acc[e]);
    }
#pragma unroll
    for (int e = 0; e < E; e++) {
#pragma unroll
        for (int o = 16; o > 0; o >>= 1) acc[e] += __shfl_xor_sync(0xFFFFFFFFu, acc[e], o);
    }

    if (lane == 0) {
        int bi = 0; float best = acc[0];
#pragma unroll
        for (int e = 1; e < E; e++) if (acc[e] > best) { best = acc[e]; bi = e; }
        int si = -1; float sec = -3.0e38f;
#pragma unroll
        for (int e = 0; e < E; e++) if (e != bi && acc[e] > sec) { sec = acc[e]; si = e; }

        float w1 = __expf(sec - best);
        float s  = 1.0f + w1;
        float w0 = 1.0f / s;
        w1       = w1 / s;

        int p0 = atomicAdd(&g_counts[bi], 1);
        g_tok[bi * T + p0] = t; g_w[bi * T + p0] = w0; g_ent[bi * T + p0] = 2 * t;
        int p1 = atomicAdd(&g_counts[si], 1);
        g_tok[si * T + p1] = t; g_w[si * T + p1] = w1; g_ent[si * T + p1] = 2 * t + 1;
    }
}

// ---------------- GEMM1: H[entry] = silu(Xt[tok] @ W1t[e] + b1[e]) ----------------
__global__ __launch_bounds__(THREADS, 2) void gemm1_kernel(const float* __restrict__ b1) {
    const int e   = blockIdx.z;
    const int cnt = g_counts[e];
    const int m0  = blockIdx.y * BM;
    if (m0 >= cnt) return;
    const int n0  = blockIdx.x * BN;

    extern __shared__ float smem[];
    __shared__ int s_tok[BM];
    __shared__ int s_ent[BM];

    const int tid = threadIdx.x;
    for (int r = tid; r < BM; r += THREADS) {
        int p = m0 + r;
        int tok = 0, ent = 0;
        if (p < cnt) { tok = g_tok[e * T + p]; ent = g_ent[e * T + p]; }
        s_tok[r] = tok; s_ent[r] = ent;
    }
    __syncthreads();

    const float* Be = g_W1t + (size_t)e * Dm * DFm;

    auto issue_stage = [&](int s, int k0) {
        float* As = smem + s * STAGE_SZ;
        float* Bs = As + A_SZ;
        unsigned sa = smem_u32(As);
        unsigned sb = smem_u32(Bs);
#pragma unroll
        for (int it = 0; it < 4; it++) {
            int c = it * THREADS + tid;        // 0..1023
            int r = c >> 3, c4 = (c & 7) << 2;
            const float* src = g_Xt + (size_t)s_tok[r] * Dm + k0 + c4;
            CP_ASYNC_CG(sa + (unsigned)(r * LDA + c4) * 4u, src);
        }
#pragma unroll
        for (int it = 0; it < 4; it++) {
            int c = it * THREADS + tid;        // 0..1023
            int r = c >> 5, c4 = (c & 31) << 2;
            const float* src = Be + (size_t)(k0 + r) * DFm + n0 + c4;
            CP_ASYNC_CG(sb + (unsigned)(r * LDB + c4) * 4u, src);
        }
        CP_ASYNC_COMMIT();
    };

    const int wid = tid >> 5;
    const int wm  = (wid & 3) * 32;     // 0,32,64,96
    const int wn  = (wid >> 2) * 64;    // 0,64

    FragC c[2][4];
#pragma unroll
    for (int i = 0; i < 2; i++)
#pragma unroll
        for (int j = 0; j < 4; j++) wmma::fill_fragment(c[i][j], 0.0f);

    constexpr int NITER = Dm / BK;      // 32
    issue_stage(0, 0);
    issue_stage(1, BK);

    for (int it = 0; it < NITER; it++) {
        if (it + 1 < NITER) { CP_ASYNC_WAIT_1(); } else { CP_ASYNC_WAIT_ALL(); }
        __syncthreads();
        if (it + 2 < NITER) issue_stage((it + 2) % STAGES, (it + 2) * BK);

        const float* As = smem + (it % STAGES) * STAGE_SZ;
        const float* Bs = As + A_SZ;
#pragma unroll
        for (int kk = 0; kk < BK; kk += 8) {
            FragA a0, a1;
            wmma::load_matrix_sync(a0, As + (wm)      * LDA + kk, LDA);
            wmma::load_matrix_sync(a1, As + (wm + 16) * LDA + kk, LDA);
            FragB bf[4];
#pragma unroll
            for (int j = 0; j < 4; j++)
                wmma::load_matrix_sync(bf[j], Bs + kk * LDB + wn + 16 * j, LDB);
#pragma unroll
            for (int j = 0; j < 4; j++) {
                wmma::mma_sync(c[0][j], a0, bf[j], c[0][j]);
                wmma::mma_sync(c[1][j], a1, bf[j], c[1][j]);
            }
        }
    }
    __syncthreads();

    // epilogue: frags -> smem C -> bias + silu -> tf32 round -> scatter
#pragma unroll
    for (int i = 0; i < 2; i++)
#pragma unroll
        for (int j = 0; j < 4; j++)
            wmma::store_matrix_sync(smem + (wm + 16 * i) * LDC + wn + 16 * j,
                                    c[i][j], LDC, wmma::mem_row_major);
    __syncthreads();

    const float* b1e = b1 + e * DFm + n0;
#pragma unroll
    for (int it = 0; it < 16; it++) {
        int idx = it * THREADS + tid;          // 0..4095
        int r = idx >> 5, c4 = (idx & 31) << 2;
        if (m0 + r < cnt) {
            float4 v  = *reinterpret_cast<const float4*>(smem + r * LDC + c4);
            float4 bb = *reinterpret_cast<const float4*>(b1e + c4);
            v.x = silu_f(v.x + bb.x); v.y = silu_f(v.y + bb.y);
            v.z = silu_f(v.z + bb.z); v.w = silu_f(v.w + bb.w);
            v = tf32_round4(v);
            *reinterpret_cast<float4*>(g_H + (size_t)s_ent[r] * DFm + n0 + c4) = v;
        }
    }
}

// ---------------- GEMM2: O[entry] = (H[entry] @ W2t[e] + b2[e]) * gate ----------------
__global__ __launch_bounds__(THREADS, 2) void gemm2_kernel(const float* __restrict__ b2) {
    const int e   = blockIdx.z;
    const int cnt = g_counts[e];
    const int m0  = blockIdx.y * BM;
    if (m0 >= cnt) return;
    const int n0  = blockIdx.x * BN;

    extern __shared__ float smem[];
    __shared__ int   s_ent[BM];
    __shared__ float s_w[BM];

    const int tid = threadIdx.x;
    for (int r = tid; r < BM; r += THREADS) {
        int p = m0 + r;
        int ent = 0; float wv = 0.0f;
        if (p < cnt) { ent = g_ent[e * T + p]; wv = g_w[e * T + p]; }
        s_ent[r] = ent; s_w[r] = wv;
    }
    __syncthreads();

    const float* Be = g_W2t + (size_t)e * DFm * Dm;

    auto issue_stage = [&](int s, int k0) {
        float* As = smem + s * STAGE_SZ;
        float* Bs = As + A_SZ;
        unsigned sa = smem_u32(As);
        unsigned sb = smem_u32(Bs);
#pragma unroll
        for (int it = 0; it < 4; it++) {
            int c = it * THREADS + tid;
            int r = c >> 3, c4 = (c & 7) << 2;
            const float* src = g_H + (size_t)s_ent[r] * DFm + k0 + c4;
            CP_ASYNC_CG(sa + (unsigned)(r * LDA + c4) * 4u, src);
        }
#pragma unroll
        for (int it = 0; it < 4; it++) {
            int c = it * THREADS + tid;
            int r = c >> 5, c4 = (c & 31) << 2;
            const float* src = Be + (size_t)(k0 + r) * Dm + n0 + c4;
            CP_ASYNC_CG(sb + (unsigned)(r * LDB + c4) * 4u, src);
        }
        CP_ASYNC_COMMIT();
    };

    const int wid = tid >> 5;
    const int wm  = (wid & 3) * 32;
    const int wn  = (wid >> 2) * 64;

    FragC c[2][4];
#pragma unroll
    for (int i = 0; i < 2; i++)
#pragma unroll
        for (int j = 0; j < 4; j++) wmma::fill_fragment(c[i][j], 0.0f);

    constexpr int NITER = DFm / BK;     // 128
    issue_stage(0, 0);
    issue_stage(1, BK);

    for (int it = 0; it < NITER; it++) {
        if (it + 1 < NITER) { CP_ASYNC_WAIT_1(); } else { CP_ASYNC_WAIT_ALL(); }
        __syncthreads();
        if (it + 2 < NITER) issue_stage((it + 2) % STAGES, (it + 2) * BK);

        const float* As = smem + (it % STAGES) * STAGE_SZ;
        const float* Bs = As + A_SZ;
#pragma unroll
        for (int kk = 0; kk < BK; kk += 8) {
            FragA a0, a1;
            wmma::load_matrix_sync(a0, As + (wm)      * LDA + kk, LDA);
            wmma::load_matrix_sync(a1, As + (wm + 16) * LDA + kk, LDA);
            FragB bf[4];
#pragma unroll
            for (int j = 0; j < 4; j++)
                wmma::load_matrix_sync(bf[j], Bs + kk * LDB + wn + 16 * j, LDB);
#pragma unroll
            for (int j = 0; j < 4; j++) {
                wmma::mma_sync(c[0][j], a0, bf[j], c[0][j]);
                wmma::mma_sync(c[1][j], a1, bf[j], c[1][j]);
            }
        }
    }
    __syncthreads();

#pragma unroll
    for (int i = 0; i < 2; i++)
#pragma unroll
        for (int j = 0; j < 4; j++)
            wmma::store_matrix_sync(smem + (wm + 16 * i) * LDC + wn + 16 * j,
                                    c[i][j], LDC, wmma::mem_row_major);
    __syncthreads();

    const float* b2e = b2 + e * Dm + n0;
#pragma unroll
    for (int it = 0; it < 16; it++) {
        int idx = it * THREADS + tid;
        int r = idx >> 5, c4 = (idx & 31) << 2;
        if (m0 + r < cnt) {
            float  gv = s_w[r];
            float4 v  = *reinterpret_cast<const float4*>(smem + r * LDC + c4);
            float4 bb = *reinterpret_cast<const float4*>(b2e + c4);
            v.x = (v.x + bb.x) * gv; v.y = (v.y + bb.y) * gv;
            v.z = (v.z + bb.z) * gv; v.w = (v.w + bb.w) * gv;
            *reinterpret_cast<float4*>(g_O + (size_t)s_ent[r] * Dm + n0 + c4) = v;
        }
    }
}

// ---------------- combine: out[t] = O[2t] + O[2t+1] ----------------
__global__ __launch_bounds__(256) void combine_kernel(float* __restrict__ out) {
    size_t i = (size_t)blockIdx.x * 256 + threadIdx.x;
    if (i >= (size_t)T * Dm / 4) return;
    int t = (int)(i / (Dm / 4));
    int c = (int)(i % (Dm / 4));
    const float4* O4 = reinterpret_cast<const float4*>(g_O);
    float4 a = O4[(size_t)(2 * t)     * (Dm / 4) + c];
    float4 b = O4[(size_t)(2 * t + 1) * (Dm / 4) + c];
    float4 r; r.x = a.x + b.x; r.y = a.y + b.y; r.z = a.z + b.z; r.w = a.w + b.w;
    reinterpret_cast<float4*>(out)[i] = r;
}

// ---------------- launch ----------------
extern "C" void kernel_launch(void* const* d_in, const int* in_sizes, int n_in,
                              void* d_out, int out_size) {
    const float* x  = (const float*)d_in[0];
    const float* gw = (const float*)d_in[1];
    const float* W1 = (const float*)d_in[2];
    const float* b1 = (const float*)d_in[3];
    const float* W2 = (const float*)d_in[4];
    const float* b2 = (const float*)d_in[5];
    float* out = (float*)d_out;

    static bool attr_set = false;
    if (!attr_set) {
        cudaFuncSetAttribute(gemm1_kernel, cudaFuncAttributeMaxDynamicSharedMemorySize, SMEM_BYTES);
        cudaFuncSetAttribute(gemm2_kernel, cudaFuncAttributeMaxDynamicSharedMemorySize, SMEM_BYTES);
        attr_set = true;
    }

    zero_counts_kernel<<<1, 32>>>();
    route_kernel<<<T / 8, 256>>>(x, gw);
    cvt_x_kernel <<<(T * Dm / 4 + 255) / 256, 256>>>(x);
    cvt_w1_kernel<<<(int)(((size_t)E * Dm * DFm / 4 + 255) / 256), 256>>>(W1);
    cvt_w2_kernel<<<(int)(((size_t)E * DFm * Dm / 4 + 255) / 256), 256>>>(W2);
    gemm1_kernel<<<dim3(DFm / BN, T / BM, E), THREADS, SMEM_BYTES>>>(b1);
    gemm2_kernel<<<dim3(Dm / BN, T / BM, E), THREADS, SMEM_BYTES>>>(b2);
    combine_kernel<<<(int)(((size_t)T * Dm / 4 + 255) / 256), 256>>>(out);
}

// round 9
// speedup vs baseline: 4.0145x; 4.0145x over previous
#include <cstdint>
#include <cuda_runtime.h>
#include <cuda_fp16.h>
#include <mma.h>

using namespace nvcuda;

// ---------------- problem constants ----------------
constexpr int T   = 16384;   // B*S tokens
constexpr int Dm  = 1024;    // model dim
constexpr int DFm = 4096;    // expert hidden dim
constexpr int E   = 8;       // experts

// ---------------- GEMM tile config (fp16 operands, fp32 accum) ----------------
constexpr int BM = 128, BN = 128, BK = 32;
constexpr int LDA = BK + 8;    // 40 halves  (80 B rows)
constexpr int LDB = BN + 8;    // 136 halves (272 B rows)
constexpr int LDC = BN + 4;    // 132 floats
constexpr int THREADS = 256;
constexpr int STAGES = 3;

constexpr int A_SZ     = BM * LDA;              // 5120 halves
constexpr int B_SZ     = BK * LDB;              // 4352 halves
constexpr int STAGE_SZ = A_SZ + B_SZ;           // 9472 halves = 18944 B
constexpr int MAIN_B   = STAGES * STAGE_SZ * 2; // 56832 B
constexpr int C_B      = BM * LDC * 4;          // 67584 B
constexpr int SMEM_BYTES = (MAIN_B > C_B ? MAIN_B : C_B);  // 67584

using FragA = wmma::fragment<wmma::matrix_a, 16, 16, 16, __half, wmma::row_major>;
using FragB = wmma::fragment<wmma::matrix_b, 16, 16, 16, __half, wmma::row_major>;
using FragC = wmma::fragment<wmma::accumulator, 16, 16, 16, float>;

// ---------------- device scratch (no allocs allowed) ----------------
__device__ int    g_counts[E];
__device__ int    g_tok[E * T];
__device__ int    g_ent[E * T];
__device__ float  g_w[E * T];
__device__ __half g_Hh[(size_t)2 * T * DFm];     // 268 MB (fp16 H)
__device__ float  g_O[(size_t)2 * T * Dm];       // 134 MB
__device__ __half g_Xh[(size_t)T * Dm];          // 33 MB
__device__ __half g_W1h[(size_t)E * Dm * DFm];   // 67 MB
__device__ __half g_W2h[(size_t)E * DFm * Dm];   // 67 MB

__device__ __forceinline__ float silu_f(float v) {
    return v / (1.0f + __expf(-v));
}

#define CP_ASYNC_CG(dst_u32, src_ptr) \
    asm volatile("cp.async.cg.shared.global [%0], [%1], 16;\n" :: "r"(dst_u32), "l"(src_ptr))
#define CP_ASYNC_COMMIT()   asm volatile("cp.async.commit_group;\n" ::)
#define CP_ASYNC_WAIT_1()   asm volatile("cp.async.wait_group 1;\n" ::)
#define CP_ASYNC_WAIT_ALL() asm volatile("cp.async.wait_group 0;\n" ::)

__device__ __forceinline__ unsigned smem_u32(const void* p) {
    return static_cast<unsigned>(__cvta_generic_to_shared(p));
}

// ---------------- fp16 pre-conversion kernels ----------------
// pack 8 fp32 -> 8 fp16 per thread (two float4 reads, one uint4 write)
__device__ __forceinline__ void cvt8(const float4* s, uint4* d, size_t i) {
    float4 a = s[2 * i], b = s[2 * i + 1];
    __half2 h0 = __floats2half2_rn(a.x, a.y);
    __half2 h1 = __floats2half2_rn(a.z, a.w);
    __half2 h2 = __floats2half2_rn(b.x, b.y);
    __half2 h3 = __floats2half2_rn(b.z, b.w);
    uint4 o;
    o.x = *reinterpret_cast<unsigned*>(&h0);
    o.y = *reinterpret_cast<unsigned*>(&h1);
    o.z = *reinterpret_cast<unsigned*>(&h2);
    o.w = *reinterpret_cast<unsigned*>(&h3);
    d[i] = o;
}

__global__ __launch_bounds__(256) void cvt_x_kernel(const float* __restrict__ src) {
    size_t i = (size_t)blockIdx.x * 256 + threadIdx.x;       // over T*Dm/8
    if (i < (size_t)T * Dm / 8)
        cvt8(reinterpret_cast<const float4*>(src), reinterpret_cast<uint4*>(g_Xh), i);
}
__global__ __launch_bounds__(256) void cvt_w1_kernel(const float* __restrict__ src) {
    size_t i = (size_t)blockIdx.x * 256 + threadIdx.x;       // over E*Dm*DFm/8
    if (i < (size_t)E * Dm * DFm / 8)
        cvt8(reinterpret_cast<const float4*>(src), reinterpret_cast<uint4*>(g_W1h), i);
}
__global__ __launch_bounds__(256) void cvt_w2_kernel(const float* __restrict__ src) {
    size_t i = (size_t)blockIdx.x * 256 + threadIdx.x;       // over E*DFm*Dm/8
    if (i < (size_t)E * DFm * Dm / 8)
        cvt8(reinterpret_cast<const float4*>(src), reinterpret_cast<uint4*>(g_W2h), i);
}

// ---------------- routing ----------------
__global__ void zero_counts_kernel() {
    if (threadIdx.x < E) g_counts[threadIdx.x] = 0;
}

__global__ __launch_bounds__(256) void route_kernel(const float* __restrict__ x,
                                                    const float* __restrict__ gw) {
    int t    = (blockIdx.x * blockDim.x + threadIdx.x) >> 5;
    int lane = threadIdx.x & 31;
    if (t >= T) return;
    const float* xr = x + (size_t)t * Dm;

    float acc[E];
#pragma unroll
    for (int e = 0; e < E; e++) acc[e] = 0.0f;
    for (int c = lane; c < Dm; c += 32) {
        float xv = __ldg(xr + c);
#pragma unroll
        for (int e = 0; e < E; e++) acc[e] = fmaf(xv, __ldg(gw + e * Dm + c), acc[e]);
    }
#pragma unroll
    for (int e = 0; e < E; e++) {
#pragma unroll
        for (int o = 16; o > 0; o >>= 1) acc[e] += __shfl_xor_sync(0xFFFFFFFFu, acc[e], o);
    }

    if (lane == 0) {
        int bi = 0; float best = acc[0];
#pragma unroll
        for (int e = 1; e < E; e++) if (acc[e] > best) { best = acc[e]; bi = e; }
        int si = -1; float sec = -3.0e38f;
#pragma unroll
        for (int e = 0; e < E; e++) if (e != bi && acc[e] > sec) { sec = acc[e]; si = e; }

        float w1 = __expf(sec - best);
        float s  = 1.0f + w1;
        float w0 = 1.0f / s;
        w1       = w1 / s;

        int p0 = atomicAdd(&g_counts[bi], 1);
        g_tok[bi * T + p0] = t; g_w[bi * T + p0] = w0; g_ent[bi * T + p0] = 2 * t;
        int p1 = atomicAdd(&g_counts[si], 1);
        g_tok[si * T + p1] = t; g_w[si * T + p1] = w1; g_ent[si * T + p1] = 2 * t + 1;
    }
}

// ---------------- GEMM1: Hh[entry] = half(silu(Xh[tok] @ W1h[e] + b1[e])) ----------------
__global__ __launch_bounds__(THREADS, 2) void gemm1_kernel(const float* __restrict__ b1) {
    const int e   = blockIdx.z;
    const int cnt = g_counts[e];
    const int m0  = blockIdx.y * BM;
    if (m0 >= cnt) return;
    const int n0  = blockIdx.x * BN;

    extern __shared__ __align__(16) unsigned char dynsmem[];
    __half* hs = reinterpret_cast<__half*>(dynsmem);
    float*  cs = reinterpret_cast<float*>(dynsmem);
    __shared__ int s_tok[BM];
    __shared__ int s_ent[BM];

    const int tid = threadIdx.x;
    for (int r = tid; r < BM; r += THREADS) {
        int p = m0 + r;
        int tok = 0, ent = 0;
        if (p < cnt) { tok = g_tok[e * T + p]; ent = g_ent[e * T + p]; }
        s_tok[r] = tok; s_ent[r] = ent;
    }
    __syncthreads();

    const __half* Be = g_W1h + (size_t)e * Dm * DFm;

    auto issue_stage = [&](int s, int k0) {
        __half* As = hs + s * STAGE_SZ;
        __half* Bs = As + A_SZ;
        unsigned sa = smem_u32(As);
        unsigned sb = smem_u32(Bs);
        // A: 128 rows x 32 halves = 512 x 16B
#pragma unroll
        for (int it = 0; it < 2; it++) {
            int c = it * THREADS + tid;        // 0..511
            int r = c >> 2, ch = (c & 3) << 3; // 4 chunks of 8 halves per row
            const __half* src = g_Xh + (size_t)s_tok[r] * Dm + k0 + ch;
            CP_ASYNC_CG(sa + (unsigned)(r * LDA + ch) * 2u, src);
        }
        // B: 32 rows x 128 halves = 512 x 16B
#pragma unroll
        for (int it = 0; it < 2; it++) {
            int c = it * THREADS + tid;        // 0..511
            int r = c >> 4, ch = (c & 15) << 3;
            const __half* src = Be + (size_t)(k0 + r) * DFm + n0 + ch;
            CP_ASYNC_CG(sb + (unsigned)(r * LDB + ch) * 2u, src);
        }
        CP_ASYNC_COMMIT();
    };

    const int wid = tid >> 5;
    const int wm  = (wid & 3) * 32;     // 0,32,64,96
    const int wn  = (wid >> 2) * 64;    // 0,64

    FragC c[2][4];
#pragma unroll
    for (int i = 0; i < 2; i++)
#pragma unroll
        for (int j = 0; j < 4; j++) wmma::fill_fragment(c[i][j], 0.0f);

    constexpr int NITER = Dm / BK;      // 32
    issue_stage(0, 0);
    issue_stage(1, BK);

    for (int it = 0; it < NITER; it++) {
        if (it + 1 < NITER) { CP_ASYNC_WAIT_1(); } else { CP_ASYNC_WAIT_ALL(); }
        __syncthreads();
        if (it + 2 < NITER) issue_stage((it + 2) % STAGES, (it + 2) * BK);

        const __half* As = hs + (it % STAGES) * STAGE_SZ;
        const __half* Bs = As + A_SZ;
#pragma unroll
        for (int kk = 0; kk < BK; kk += 16) {
            FragA a0, a1;
            wmma::load_matrix_sync(a0, As + (wm)      * LDA + kk, LDA);
            wmma::load_matrix_sync(a1, As + (wm + 16) * LDA + kk, LDA);
            FragB bf[4];
#pragma unroll
            for (int j = 0; j < 4; j++)
                wmma::load_matrix_sync(bf[j], Bs + kk * LDB + wn + 16 * j, LDB);
#pragma unroll
            for (int j = 0; j < 4; j++) {
                wmma::mma_sync(c[0][j], a0, bf[j], c[0][j]);
                wmma::mma_sync(c[1][j], a1, bf[j], c[1][j]);
            }
        }
    }
    __syncthreads();

    // epilogue: frags -> smem C(fp32) -> bias + silu -> half -> scatter
#pragma unroll
    for (int i = 0; i < 2; i++)
#pragma unroll
        for (int j = 0; j < 4; j++)
            wmma::store_matrix_sync(cs + (wm + 16 * i) * LDC + wn + 16 * j,
                                    c[i][j], LDC, wmma::mem_row_major);
    __syncthreads();

    const float* b1e = b1 + e * DFm + n0;
#pragma unroll
    for (int it = 0; it < 16; it++) {
        int idx = it * THREADS + tid;          // 0..4095
        int r = idx >> 5, c4 = (idx & 31) << 2;
        if (m0 + r < cnt) {
            float4 v  = *reinterpret_cast<const float4*>(cs + r * LDC + c4);
            float4 bb = *reinterpret_cast<const float4*>(b1e + c4);
            v.x = silu_f(v.x + bb.x); v.y = silu_f(v.y + bb.y);
            v.z = silu_f(v.z + bb.z); v.w = silu_f(v.w + bb.w);
            __half2 h0 = __floats2half2_rn(v.x, v.y);
            __half2 h1 = __floats2half2_rn(v.z, v.w);
            uint2 o;
            o.x = *reinterpret_cast<unsigned*>(&h0);
            o.y = *reinterpret_cast<unsigned*>(&h1);
            *reinterpret_cast<uint2*>(g_Hh + (size_t)s_ent[r] * DFm + n0 + c4) = o;
        }
    }
}

// ---------------- GEMM2: O[entry] = (Hh[entry] @ W2h[e] + b2[e]) * gate ----------------
__global__ __launch_bounds__(THREADS, 2) void gemm2_kernel(const float* __restrict__ b2) {
    const int e   = blockIdx.z;
    const int cnt = g_counts[e];
    const int m0  = blockIdx.y * BM;
    if (m0 >= cnt) return;
    const int n0  = blockIdx.x * BN;

    extern __shared__ __align__(16) unsigned char dynsmem[];
    __half* hs = reinterpret_cast<__half*>(dynsmem);
    float*  cs = reinterpret_cast<float*>(dynsmem);
    __shared__ int   s_ent[BM];
    __shared__ float s_w[BM];

    const int tid = threadIdx.x;
    for (int r = tid; r < BM; r += THREADS) {
        int p = m0 + r;
        int ent = 0; float wv = 0.0f;
        if (p < cnt) { ent = g_ent[e * T + p]; wv = g_w[e * T + p]; }
        s_ent[r] = ent; s_w[r] = wv;
    }
    __syncthreads();

    const __half* Be = g_W2h + (size_t)e * DFm * Dm;

    auto issue_stage = [&](int s, int k0) {
        __half* As = hs + s * STAGE_SZ;
        __half* Bs = As + A_SZ;
        unsigned sa = smem_u32(As);
        unsigned sb = smem_u32(Bs);
#pragma unroll
        for (int it = 0; it < 2; it++) {
            int c = it * THREADS + tid;
            int r = c >> 2, ch = (c & 3) << 3;
            const __half* src = g_Hh + (size_t)s_ent[r] * DFm + k0 + ch;
            CP_ASYNC_CG(sa + (unsigned)(r * LDA + ch) * 2u, src);
        }
#pragma unroll
        for (int it = 0; it < 2; it++) {
            int c = it * THREADS + tid;
            int r = c >> 4, ch = (c & 15) << 3;
            const __half* src = Be + (size_t)(k0 + r) * Dm + n0 + ch;
            CP_ASYNC_CG(sb + (unsigned)(r * LDB + ch) * 2u, src);
        }
        CP_ASYNC_COMMIT();
    };

    const int wid = tid >> 5;
    const int wm  = (wid & 3) * 32;
    const int wn  = (wid >> 2) * 64;

    FragC c[2][4];
#pragma unroll
    for (int i = 0; i < 2; i++)
#pragma unroll
        for (int j = 0; j < 4; j++) wmma::fill_fragment(c[i][j], 0.0f);

    constexpr int NITER = DFm / BK;     // 128
    issue_stage(0, 0);
    issue_stage(1, BK);

    for (int it = 0; it < NITER; it++) {
        if (it + 1 < NITER) { CP_ASYNC_WAIT_1(); } else { CP_ASYNC_WAIT_ALL(); }
        __syncthreads();
        if (it + 2 < NITER) issue_stage((it + 2) % STAGES, (it + 2) * BK);

        const __half* As = hs + (it % STAGES) * STAGE_SZ;
        const __half* Bs = As + A_SZ;
#pragma unroll
        for (int kk = 0; kk < BK; kk += 16) {
            FragA a0, a1;
            wmma::load_matrix_sync(a0, As + (wm)      * LDA + kk, LDA);
            wmma::load_matrix_sync(a1, As + (wm + 16) * LDA + kk, LDA);
            FragB bf[4];
#pragma unroll
            for (int j = 0; j < 4; j++)
                wmma::load_matrix_sync(bf[j], Bs + kk * LDB + wn + 16 * j, LDB);
#pragma unroll
            for (int j = 0; j < 4; j++) {
                wmma::mma_sync(c[0][j], a0, bf[j], c[0][j]);
                wmma::mma_sync(c[1][j], a1, bf[j], c[1][j]);
            }
        }
    }
    __syncthreads();

#pragma unroll
    for (int i = 0; i < 2; i++)
#pragma unroll
        for (int j = 0; j < 4; j++)
            wmma::store_matrix_sync(cs + (wm + 16 * i) * LDC + wn + 16 * j,
                                    c[i][j], LDC, wmma::mem_row_major);
    __syncthreads();

    const float* b2e = b2 + e * Dm + n0;
#pragma unroll
    for (int it = 0; it < 16; it++) {
        int idx = it * THREADS + tid;
        int r = idx >> 5, c4 = (idx & 31) << 2;
        if (m0 + r < cnt) {
            float  gv = s_w[r];
            float4 v  = *reinterpret_cast<const float4*>(cs + r * LDC + c4);
            float4 bb = *reinterpret_cast<const float4*>(b2e + c4);
            v.x = (v.x + bb.x) * gv; v.y = (v.y + bb.y) * gv;
            v.z = (v.z + bb.z) * gv; v.w = (v.w + bb.w) * gv;
            *reinterpret_cast<float4*>(g_O + (size_t)s_ent[r] * Dm + n0 + c4) = v;
        }
    }
}

// ---------------- combine: out[t] = O[2t] + O[2t+1] ----------------
__global__ __launch_bounds__(256) void combine_kernel(float* __restrict__ out) {
    size_t i = (size_t)blockIdx.x * 256 + threadIdx.x;
    if (i >= (size_t)T * Dm / 4) return;
    int t = (int)(i / (Dm / 4));
    int c = (int)(i % (Dm / 4));
    const float4* O4 = reinterpret_cast<const float4*>(g_O);
    float4 a = O4[(size_t)(2 * t)     * (Dm / 4) + c];
    float4 b = O4[(size_t)(2 * t + 1) * (Dm / 4) + c];
    float4 r; r.x = a.x + b.x; r.y = a.y + b.y; r.z = a.z + b.z; r.w = a.w + b.w;
    reinterpret_cast<float4*>(out)[i] = r;
}

// ---------------- launch ----------------
extern "C" void kernel_launch(void* const* d_in, const int* in_sizes, int n_in,
                              void* d_out, int out_size) {
    const float* x  = (const float*)d_in[0];
    const float* gw = (const float*)d_in[1];
    const float* W1 = (const float*)d_in[2];
    const float* b1 = (const float*)d_in[3];
    const float* W2 = (const float*)d_in[4];
    const float* b2 = (const float*)d_in[5];
    float* out = (float*)d_out;

    static bool attr_set = false;
    if (!attr_set) {
        cudaFuncSetAttribute(gemm1_kernel, cudaFuncAttributeMaxDynamicSharedMemorySize, SMEM_BYTES);
        cudaFuncSetAttribute(gemm2_kernel, cudaFuncAttributeMaxDynamicSharedMemorySize, SMEM_BYTES);
        attr_set = true;
    }

    zero_counts_kernel<<<1, 32>>>();
    route_kernel<<<T / 8, 256>>>(x, gw);
    cvt_x_kernel <<<(int)(((size_t)T * Dm / 8 + 255) / 256), 256>>>(x);
    cvt_w1_kernel<<<(int)(((size_t)E * Dm * DFm / 8 + 255) / 256), 256>>>(W1);
    cvt_w2_kernel<<<(int)(((size_t)E * DFm * Dm / 8 + 255) / 256), 256>>>(W2);
    gemm1_kernel<<<dim3(DFm / BN, T / BM, E), THREADS, SMEM_BYTES>>>(b1);
    gemm2_kernel<<<dim3(Dm / BN, T / BM, E), THREADS, SMEM_BYTES>>>(b2);
    combine_kernel<<<(int)(((size_t)T * Dm / 4 + 255) / 256), 256>>>(out);
}

// round 10
// speedup vs baseline: 4.0534x; 1.0097x over previous
#include <cstdint>
#include <cuda_runtime.h>
#include <cuda_fp16.h>
#include <mma.h>

using namespace nvcuda;

// ---------------- problem constants ----------------
constexpr int T   = 16384;   // B*S tokens
constexpr int Dm  = 1024;    // model dim
constexpr int DFm = 4096;    // expert hidden dim
constexpr int E   = 8;       // experts

// ---------------- GEMM tile config (fp16 operands, fp32 accum) ----------------
constexpr int BM = 128, BN = 128, BK = 64;
constexpr int LDA = BK + 8;    // 72 halves  (144 B rows)
constexpr int LDB = BN + 8;    // 136 halves (272 B rows)
constexpr int LDC = BN + 4;    // 132 floats
constexpr int THREADS = 256;
constexpr int STAGES = 3;

constexpr int A_SZ     = BM * LDA;              // 9216 halves
constexpr int B_SZ     = BK * LDB;              // 8704 halves
constexpr int STAGE_SZ = A_SZ + B_SZ;           // 17920 halves = 35840 B
constexpr int MAIN_B   = STAGES * STAGE_SZ * 2; // 107520 B
constexpr int C_B      = BM * LDC * 4;          // 67584 B
constexpr int SMEM_BYTES = (MAIN_B > C_B ? MAIN_B : C_B);  // 107520

using FragA = wmma::fragment<wmma::matrix_a, 16, 16, 16, __half, wmma::row_major>;
using FragB = wmma::fragment<wmma::matrix_b, 16, 16, 16, __half, wmma::row_major>;
using FragC = wmma::fragment<wmma::accumulator, 16, 16, 16, float>;

// ---------------- device scratch (no allocs allowed) ----------------
__device__ int    g_counts[E];
__device__ int    g_tok[E * T];
__device__ int    g_ent[E * T];
__device__ float  g_w[E * T];
__device__ __half g_Hh[(size_t)2 * T * DFm];     // 268 MB (fp16 H)
__device__ float  g_O[(size_t)2 * T * Dm];       // 134 MB
__device__ __half g_Xh[(size_t)T * Dm];          // 33 MB
__device__ __half g_W1h[(size_t)E * Dm * DFm];   // 67 MB
__device__ __half g_W2h[(size_t)E * DFm * Dm];   // 67 MB

__device__ __forceinline__ float silu_f(float v) {
    return v / (1.0f + __expf(-v));
}

#define CP_ASYNC_CG(dst_u32, src_ptr) \
    asm volatile("cp.async.cg.shared.global [%0], [%1], 16;\n" :: "r"(dst_u32), "l"(src_ptr))
#define CP_ASYNC_COMMIT()   asm volatile("cp.async.commit_group;\n" ::)
#define CP_ASYNC_WAIT_1()   asm volatile("cp.async.wait_group 1;\n" ::)
#define CP_ASYNC_WAIT_ALL() asm volatile("cp.async.wait_group 0;\n" ::)

__device__ __forceinline__ unsigned smem_u32(const void* p) {
    return static_cast<unsigned>(__cvta_generic_to_shared(p));
}

// ---------------- fp16 pre-conversion kernels ----------------
__device__ __forceinline__ void cvt8(const float4* s, uint4* d, size_t i) {
    float4 a = s[2 * i], b = s[2 * i + 1];
    __half2 h0 = __floats2half2_rn(a.x, a.y);
    __half2 h1 = __floats2half2_rn(a.z, a.w);
    __half2 h2 = __floats2half2_rn(b.x, b.y);
    __half2 h3 = __floats2half2_rn(b.z, b.w);
    uint4 o;
    o.x = *reinterpret_cast<unsigned*>(&h0);
    o.y = *reinterpret_cast<unsigned*>(&h1);
    o.z = *reinterpret_cast<unsigned*>(&h2);
    o.w = *reinterpret_cast<unsigned*>(&h3);
    d[i] = o;
}

__global__ __launch_bounds__(256) void cvt_x_kernel(const float* __restrict__ src) {
    size_t i = (size_t)blockIdx.x * 256 + threadIdx.x;
    if (i < (size_t)T * Dm / 8)
        cvt8(reinterpret_cast<const float4*>(src), reinterpret_cast<uint4*>(g_Xh), i);
}
__global__ __launch_bounds__(256) void cvt_w1_kernel(const float* __restrict__ src) {
    size_t i = (size_t)blockIdx.x * 256 + threadIdx.x;
    if (i < (size_t)E * Dm * DFm / 8)
        cvt8(reinterpret_cast<const float4*>(src), reinterpret_cast<uint4*>(g_W1h), i);
}
__global__ __launch_bounds__(256) void cvt_w2_kernel(const float* __restrict__ src) {
    size_t i = (size_t)blockIdx.x * 256 + threadIdx.x;
    if (i < (size_t)E * DFm * Dm / 8)
        cvt8(reinterpret_cast<const float4*>(src), reinterpret_cast<uint4*>(g_W2h), i);
}

// ---------------- routing ----------------
__global__ void zero_counts_kernel() {
    if (threadIdx.x < E) g_counts[threadIdx.x] = 0;
}

__global__ __launch_bounds__(256) void route_kernel(const float* __restrict__ x,
                                                    const float* __restrict__ gw) {
    int t    = (blockIdx.x * blockDim.x + threadIdx.x) >> 5;
    int lane = threadIdx.x & 31;
    if (t >= T) return;
    const float* xr = x + (size_t)t * Dm;

    float acc[E];
#pragma unroll
    for (int e = 0; e < E; e++) acc[e] = 0.0f;
    for (int c = lane; c < Dm; c += 32) {
        float xv = __ldg(xr + c);
#pragma unroll
        for (int e = 0; e < E; e++) acc[e] = fmaf(xv, __ldg(gw + e * Dm + c), acc[e]);
    }
#pragma unroll
    for (int e = 0; e < E; e++) {
#pragma unroll
        for (int o = 16; o > 0; o >>= 1) acc[e] += __shfl_xor_sync(0xFFFFFFFFu, acc[e], o);
    }

    if (lane == 0) {
        int bi = 0; float best = acc[0];
#pragma unroll
        for (int e = 1; e < E; e++) if (acc[e] > best) { best = acc[e]; bi = e; }
        int si = -1; float sec = -3.0e38f;
#pragma unroll
        for (int e = 0; e < E; e++) if (e != bi && acc[e] > sec) { sec = acc[e]; si = e; }

        float w1 = __expf(sec - best);
        float s  = 1.0f + w1;
        float w0 = 1.0f / s;
        w1       = w1 / s;

        int p0 = atomicAdd(&g_counts[bi], 1);
        g_tok[bi * T + p0] = t; g_w[bi * T + p0] = w0; g_ent[bi * T + p0] = 2 * t;
        int p1 = atomicAdd(&g_counts[si], 1);
        g_tok[si * T + p1] = t; g_w[si * T + p1] = w1; g_ent[si * T + p1] = 2 * t + 1;
    }
}

// ---------------- GEMM1: Hh[entry] = half(silu(Xh[tok] @ W1h[e] + b1[e])) ----------------
__global__ __launch_bounds__(THREADS, 2) void gemm1_kernel(const float* __restrict__ b1) {
    const int e   = blockIdx.z;
    const int cnt = g_counts[e];
    const int m0  = blockIdx.y * BM;
    if (m0 >= cnt) return;
    const int n0  = blockIdx.x * BN;

    extern __shared__ __align__(16) unsigned char dynsmem[];
    __half* hs = reinterpret_cast<__half*>(dynsmem);
    float*  cs = reinterpret_cast<float*>(dynsmem);
    __shared__ int s_tok[BM];
    __shared__ int s_ent[BM];

    const int tid = threadIdx.x;
    for (int r = tid; r < BM; r += THREADS) {
        int p = m0 + r;
        int tok = 0, ent = 0;
        if (p < cnt) { tok = g_tok[e * T + p]; ent = g_ent[e * T + p]; }
        s_tok[r] = tok; s_ent[r] = ent;
    }
    __syncthreads();

    const __half* Be = g_W1h + (size_t)e * Dm * DFm;

    auto issue_stage = [&](int s, int k0) {
        __half* As = hs + s * STAGE_SZ;
        __half* Bs = As + A_SZ;
        unsigned sa = smem_u32(As);
        unsigned sb = smem_u32(Bs);
        // A: 128 rows x 64 halves = 1024 x 16B
#pragma unroll
        for (int it = 0; it < 4; it++) {
            int c = it * THREADS + tid;        // 0..1023
            int r = c >> 3, ch = (c & 7) << 3; // 8 chunks of 8 halves per row
            const __half* src = g_Xh + (size_t)s_tok[r] * Dm + k0 + ch;
            CP_ASYNC_CG(sa + (unsigned)(r * LDA + ch) * 2u, src);
        }
        // B: 64 rows x 128 halves = 1024 x 16B
#pragma unroll
        for (int it = 0; it < 4; it++) {
            int c = it * THREADS + tid;        // 0..1023
            int r = c >> 4, ch = (c & 15) << 3;
            const __half* src = Be + (size_t)(k0 + r) * DFm + n0 + ch;
            CP_ASYNC_CG(sb + (unsigned)(r * LDB + ch) * 2u, src);
        }
        CP_ASYNC_COMMIT();
    };

    const int wid = tid >> 5;
    const int wm  = (wid & 3) * 32;     // 0,32,64,96
    const int wn  = (wid >> 2) * 64;    // 0,64

    FragC c[2][4];
#pragma unroll
    for (int i = 0; i < 2; i++)
#pragma unroll
        for (int j = 0; j < 4; j++) wmma::fill_fragment(c[i][j], 0.0f);

    constexpr int NITER = Dm / BK;      // 16
    issue_stage(0, 0);
    issue_stage(1, BK);

    for (int it = 0; it < NITER; it++) {
        if (it + 1 < NITER) { CP_ASYNC_WAIT_1(); } else { CP_ASYNC_WAIT_ALL(); }
        __syncthreads();
        if (it + 2 < NITER) issue_stage((it + 2) % STAGES, (it + 2) * BK);

        const __half* As = hs + (it % STAGES) * STAGE_SZ;
        const __half* Bs = As + A_SZ;
#pragma unroll
        for (int kk = 0; kk < BK; kk += 16) {
            FragA a0, a1;
            wmma::load_matrix_sync(a0, As + (wm)      * LDA + kk, LDA);
            wmma::load_matrix_sync(a1, As + (wm + 16) * LDA + kk, LDA);
            FragB bf[4];
#pragma unroll
            for (int j = 0; j < 4; j++)
                wmma::load_matrix_sync(bf[j], Bs + kk * LDB + wn + 16 * j, LDB);
#pragma unroll
            for (int j = 0; j < 4; j++) {
                wmma::mma_sync(c[0][j], a0, bf[j], c[0][j]);
                wmma::mma_sync(c[1][j], a1, bf[j], c[1][j]);
            }
        }
        __syncthreads();
    }

    // epilogue: frags -> smem C(fp32) -> bias + silu -> half -> scatter
#pragma unroll
    for (int i = 0; i < 2; i++)
#pragma unroll
        for (int j = 0; j < 4; j++)
            wmma::store_matrix_sync(cs + (wm + 16 * i) * LDC + wn + 16 * j,
                                    c[i][j], LDC, wmma::mem_row_major);
    __syncthreads();

    const float* b1e = b1 + e * DFm + n0;
#pragma unroll
    for (int it = 0; it < 16; it++) {
        int idx = it * THREADS + tid;          // 0..4095
        int r = idx >> 5, c4 = (idx & 31) << 2;
        if (m0 + r < cnt) {
            float4 v  = *reinterpret_cast<const float4*>(cs + r * LDC + c4);
            float4 bb = *reinterpret_cast<const float4*>(b1e + c4);
            v.x = silu_f(v.x + bb.x); v.y = silu_f(v.y + bb.y);
            v.z = silu_f(v.z + bb.z); v.w = silu_f(v.w + bb.w);
            __half2 h0 = __floats2half2_rn(v.x, v.y);
            __half2 h1 = __floats2half2_rn(v.z, v.w);
            uint2 o;
            o.x = *reinterpret_cast<unsigned*>(&h0);
            o.y = *reinterpret_cast<unsigned*>(&h1);
            *reinterpret_cast<uint2*>(g_Hh + (size_t)s_ent[r] * DFm + n0 + c4) = o;
        }
    }
}

// ---------------- GEMM2: O[entry] = (Hh[entry] @ W2h[e] + b2[e]) * gate ----------------
__global__ __launch_bounds__(THREADS, 2) void gemm2_kernel(const float* __restrict__ b2) {
    const int e   = blockIdx.z;
    const int cnt = g_counts[e];
    const int m0  = blockIdx.y * BM;
    if (m0 >= cnt) return;
    const int n0  = blockIdx.x * BN;

    extern __shared__ __align__(16) unsigned char dynsmem[];
    __half* hs = reinterpret_cast<__half*>(dynsmem);
    float*  cs = reinterpret_cast<float*>(dynsmem);
    __shared__ int   s_ent[BM];
    __shared__ float s_w[BM];

    const int tid = threadIdx.x;
    for (int r = tid; r < BM; r += THREADS) {
        int p = m0 + r;
        int ent = 0; float wv = 0.0f;
        if (p < cnt) { ent = g_ent[e * T + p]; wv = g_w[e * T + p]; }
        s_ent[r] = ent; s_w[r] = wv;
    }
    __syncthreads();

    const __half* Be = g_W2h + (size_t)e * DFm * Dm;

    auto issue_stage = [&](int s, int k0) {
        __half* As = hs + s * STAGE_SZ;
        __half* Bs = As + A_SZ;
        unsigned sa = smem_u32(As);
        unsigned sb = smem_u32(Bs);
#pragma unroll
        for (int it = 0; it < 4; it++) {
            int c = it * THREADS + tid;
            int r = c >> 3, ch = (c & 7) << 3;
            const __half* src = g_Hh + (size_t)s_ent[r] * DFm + k0 + ch;
            CP_ASYNC_CG(sa + (unsigned)(r * LDA + ch) * 2u, src);
        }
#pragma unroll
        for (int it = 0; it < 4; it++) {
            int c = it * THREADS + tid;
            int r = c >> 4, ch = (c & 15) << 3;
            const __half* src = Be + (size_t)(k0 + r) * Dm + n0 + ch;
            CP_ASYNC_CG(sb + (unsigned)(r * LDB + ch) * 2u, src);
        }
        CP_ASYNC_COMMIT();
    };

    const int wid = tid >> 5;
    const int wm  = (wid & 3) * 32;
    const int wn  = (wid >> 2) * 64;

    FragC c[2][4];
#pragma unroll
    for (int i = 0; i < 2; i++)
#pragma unroll
        for (int j = 0; j < 4; j++) wmma::fill_fragment(c[i][j], 0.0f);

    constexpr int NITER = DFm / BK;     // 64
    issue_stage(0, 0);
    issue_stage(1, BK);

    for (int it = 0; it < NITER; it++) {
        if (it + 1 < NITER) { CP_ASYNC_WAIT_1(); } else { CP_ASYNC_WAIT_ALL(); }
        __syncthreads();
        if (it + 2 < NITER) issue_stage((it + 2) % STAGES, (it + 2) * BK);

        const __half* As = hs + (it % STAGES) * STAGE_SZ;
        const __half* Bs = As + A_SZ;
#pragma unroll
        for (int kk = 0; kk < BK; kk += 16) {
            FragA a0, a1;
            wmma::load_matrix_sync(a0, As + (wm)      * LDA + kk, LDA);
            wmma::load_matrix_sync(a1, As + (wm + 16) * LDA + kk, LDA);
            FragB bf[4];
#pragma unroll
            for (int j = 0; j < 4; j++)
                wmma::load_matrix_sync(bf[j], Bs + kk * LDB + wn + 16 * j, LDB);
#pragma unroll
            for (int j = 0; j < 4; j++) {
                wmma::mma_sync(c[0][j], a0, bf[j], c[0][j]);
                wmma::mma_sync(c[1][j], a1, bf[j], c[1][j]);
            }
        }
        __syncthreads();
    }

#pragma unroll
    for (int i = 0; i < 2; i++)
#pragma unroll
        for (int j = 0; j < 4; j++)
            wmma::store_matrix_sync(cs + (wm + 16 * i) * LDC + wn + 16 * j,
                                    c[i][j], LDC, wmma::mem_row_major);
    __syncthreads();

    const float* b2e = b2 + e * Dm + n0;
#pragma unroll
    for (int it = 0; it < 16; it++) {
        int idx = it * THREADS + tid;
        int r = idx >> 5, c4 = (idx & 31) << 2;
        if (m0 + r < cnt) {
            float  gv = s_w[r];
            float4 v  = *reinterpret_cast<const float4*>(cs + r * LDC + c4);
            float4 bb = *reinterpret_cast<const float4*>(b2e + c4);
            v.x = (v.x + bb.x) * gv; v.y = (v.y + bb.y) * gv;
            v.z = (v.z + bb.z) * gv; v.w = (v.w + bb.w) * gv;
            *reinterpret_cast<float4*>(g_O + (size_t)s_ent[r] * Dm + n0 + c4) = v;
        }
    }
}

// ---------------- combine: out[t] = O[2t] + O[2t+1] ----------------
__global__ __launch_bounds__(256) void combine_kernel(float* __restrict__ out) {
    size_t i = (size_t)blockIdx.x * 256 + threadIdx.x;
    if (i >= (size_t)T * Dm / 4) return;
    int t = (int)(i / (Dm / 4));
    int c = (int)(i % (Dm / 4));
    const float4* O4 = reinterpret_cast<const float4*>(g_O);
    float4 a = O4[(size_t)(2 * t)     * (Dm / 4) + c];
    float4 b = O4[(size_t)(2 * t + 1) * (Dm / 4) + c];
    float4 r; r.x = a.x + b.x; r.y = a.y + b.y; r.z = a.z + b.z; r.w = a.w + b.w;
    reinterpret_cast<float4*>(out)[i] = r;
}

// ---------------- launch ----------------
extern "C" void kernel_launch(void* const* d_in, const int* in_sizes, int n_in,
                              void* d_out, int out_size) {
    const float* x  = (const float*)d_in[0];
    const float* gw = (const float*)d_in[1];
    const float* W1 = (const float*)d_in[2];
    const float* b1 = (const float*)d_in[3];
    const float* W2 = (const float*)d_in[4];
    const float* b2 = (const float*)d_in[5];
    float* out = (float*)d_out;

    static bool attr_set = false;
    if (!attr_set) {
        cudaFuncSetAttribute(gemm1_kernel, cudaFuncAttributeMaxDynamicSharedMemorySize, SMEM_BYTES);
        cudaFuncSetAttribute(gemm2_kernel, cudaFuncAttributeMaxDynamicSharedMemorySize, SMEM_BYTES);
        attr_set = true;
    }

    zero_counts_kernel<<<1, 32>>>();
    route_kernel<<<T / 8, 256>>>(x, gw);
    cvt_x_kernel <<<(int)(((size_t)T * Dm / 8 + 255) / 256), 256>>>(x);
    cvt_w1_kernel<<<(int)(((size_t)E * Dm * DFm / 8 + 255) / 256), 256>>>(W1);
    cvt_w2_kernel<<<(int)(((size_t)E * DFm * Dm / 8 + 255) / 256), 256>>>(W2);
    gemm1_kernel<<<dim3(DFm / BN, T / BM, E), THREADS, SMEM_BYTES>>>(b1);
    gemm2_kernel<<<dim3(Dm / BN, T / BM, E), THREADS, SMEM_BYTES>>>(b2);
    combine_kernel<<<(int)(((size_t)T * Dm / 4 + 255) / 256), 256>>>(out);
}